// round 2
// baseline (speedup 1.0000x reference)
#include <cuda_runtime.h>
#include <cuda_bf16.h>
#include <math.h>

#define B_   128
#define S_   2048
#define H_   256
#define VSZ  32000
#define KP   264   // padded smem row stride (bf16 elems) -> conflict-free mma frag loads

#define ATTN_SMEM   (256*KP*2 + 64*KP*2 + 256*4 + 256*4 + 64*4*4)
#define LOGITS_SMEM (128*KP*2 + 128*KP*2)

// ---------------- scratch (device globals; no allocation allowed) ----------------
__device__ __align__(16) float g_scores[B_*S_];
__device__ __align__(16) float g_attn[B_*S_];
__device__ __align__(16) float g_partial[8*B_*H_];
__device__ __align__(16) float g_w2h[B_*H_];
__device__ __align__(16) float g_res[B_*H_];
__device__ __align__(16) float g_h0[B_*H_];
__device__ __align__(16) float g_h1[B_*H_];
__device__ __align__(16) __nv_bfloat16 g_W1T[H_*H_];   // W1 transposed, bf16

// ---------------- mma.sync m16n8k16 bf16 ----------------
__device__ __forceinline__ void mma16816(float (&d)[4], const unsigned (&a)[4], const unsigned (&b)[2]) {
    asm volatile(
        "mma.sync.aligned.m16n8k16.row.col.f32.bf16.bf16.f32 "
        "{%0,%1,%2,%3}, {%4,%5,%6,%7}, {%8,%9}, {%0,%1,%2,%3};\n"
        : "+f"(d[0]), "+f"(d[1]), "+f"(d[2]), "+f"(d[3])
        : "r"(a[0]), "r"(a[1]), "r"(a[2]), "r"(a[3]),
          "r"(b[0]), "r"(b[1]));
}

// ---------------- K0: W1 [K][N] fp32 -> W1T [N][K] bf16 (tiled transpose) ----------------
__global__ void k_convW1(const float* __restrict__ W1) {
    __shared__ float tile[32][33];
    int kt = blockIdx.x, nt = blockIdx.y;
    int tx = threadIdx.x, ty = threadIdx.y;
    tile[ty][tx] = W1[(kt*32 + ty) * H_ + nt*32 + tx];
    __syncthreads();
    g_W1T[(nt*32 + ty) * H_ + kt*32 + tx] = __float2bfloat16(tile[tx][ty]);
}

// ---------------- K1: w2h = hidden[-1] @ W2 + b2  (fp32) ----------------
__global__ void k_w2h(const float* __restrict__ hidden, const float* __restrict__ W2,
                      const float* __restrict__ b2) {
    __shared__ __align__(16) float hsm[H_];
    int b = blockIdx.x, k = threadIdx.x;
    hsm[k] = hidden[(B_ + b) * H_ + k];   // hidden[1]
    __syncthreads();
    float acc = b2[k];
#pragma unroll 8
    for (int h = 0; h < H_; h++) acc += hsm[h] * W2[h * H_ + k];
    g_w2h[b * H_ + k] = acc;
}

// ---------------- K2: fused scores[b,s] = V . tanh(enc[b,s,:]@W1 + w2h[b,:]) ----------------
// bf16 mma.sync GEMM, CTA tile 64(S) x 256(H), K=256 fully resident in smem.
// grid (4, 128): blockIdx.y = b, blockIdx.x = s-chunk of 512 (8 tiles of 64).
__global__ __launch_bounds__(256, 1) void k_attn(const float* __restrict__ enc,
                                                 const float* __restrict__ Vp) {
    extern __shared__ unsigned char smem[];
    __nv_bfloat16* Bs  = (__nv_bfloat16*)smem;                         // [256][KP]  W1T
    __nv_bfloat16* As  = (__nv_bfloat16*)(smem + 256*KP*2);            // [64][KP]   enc tile
    float* w2h_s = (float*)(smem + 256*KP*2 + 64*KP*2);                // [256]
    float* V_s   = w2h_s + 256;                                        // [256]
    float* sred  = V_s + 256;                                          // [64][4]

    const int tid  = threadIdx.x;
    const int warp = tid >> 5, lane = tid & 31;
    const int g = lane >> 2, tg = lane & 3;
    const int wm = warp & 1, wn = warp >> 1;      // warp grid 2(M) x 4(N)
    const int b = blockIdx.y;

    // load W1T (bf16) into Bs with pad
    const uint4* src = (const uint4*)g_W1T;
    for (int i = tid; i < 8192; i += 256) {
        int e = i * 8, n = e >> 8, k = e & 255;
        *(uint4*)(Bs + n * KP + k) = src[i];
    }
    w2h_s[tid] = g_w2h[b * H_ + tid];
    V_s[tid]   = Vp[tid];

    for (int t = 0; t < 8; t++) {
        const int s0 = blockIdx.x * 512 + t * 64;
        // load + convert enc tile [64][256]
        const float4* ev = (const float4*)(enc + ((size_t)b * S_ + s0) * H_);
        for (int i = tid; i < 4096; i += 256) {
            int e = i * 4, r = e >> 8, k = e & 255;
            float4 v = ev[i];
            *(__nv_bfloat162*)(As + r * KP + k)     = __floats2bfloat162_rn(v.x, v.y);
            *(__nv_bfloat162*)(As + r * KP + k + 2) = __floats2bfloat162_rn(v.z, v.w);
        }
        __syncthreads();

        float acc[2][8][4] = {};
#pragma unroll
        for (int k0 = 0; k0 < 256; k0 += 16) {
            unsigned a[2][4], bb[8][2];
#pragma unroll
            for (int mi = 0; mi < 2; mi++) {
                int r = wm * 32 + mi * 16;
                a[mi][0] = *(const unsigned*)(As + (r + g)     * KP + k0     + tg*2);
                a[mi][1] = *(const unsigned*)(As + (r + g + 8) * KP + k0     + tg*2);
                a[mi][2] = *(const unsigned*)(As + (r + g)     * KP + k0 + 8 + tg*2);
                a[mi][3] = *(const unsigned*)(As + (r + g + 8) * KP + k0 + 8 + tg*2);
            }
#pragma unroll
            for (int ni = 0; ni < 8; ni++) {
                int n = wn * 64 + ni * 8 + g;
                bb[ni][0] = *(const unsigned*)(Bs + n * KP + k0     + tg*2);
                bb[ni][1] = *(const unsigned*)(Bs + n * KP + k0 + 8 + tg*2);
            }
#pragma unroll
            for (int mi = 0; mi < 2; mi++)
#pragma unroll
                for (int ni = 0; ni < 8; ni++)
                    mma16816(acc[mi][ni], a[mi], bb[ni]);
        }

        // epilogue: tanh(+w2h) * V, reduce over H
#pragma unroll
        for (int mi = 0; mi < 2; mi++) {
            float pl = 0.f, ph = 0.f;
#pragma unroll
            for (int ni = 0; ni < 8; ni++) {
                int c = wn * 64 + ni * 8 + tg * 2;
                pl += V_s[c]   * tanhf(acc[mi][ni][0] + w2h_s[c])
                    + V_s[c+1] * tanhf(acc[mi][ni][1] + w2h_s[c+1]);
                ph += V_s[c]   * tanhf(acc[mi][ni][2] + w2h_s[c])
                    + V_s[c+1] * tanhf(acc[mi][ni][3] + w2h_s[c+1]);
            }
            pl += __shfl_xor_sync(0xffffffffu, pl, 1); pl += __shfl_xor_sync(0xffffffffu, pl, 2);
            ph += __shfl_xor_sync(0xffffffffu, ph, 1); ph += __shfl_xor_sync(0xffffffffu, ph, 2);
            if (tg == 0) {
                sred[(wm*32 + mi*16 + g)     * 4 + wn] = pl;
                sred[(wm*32 + mi*16 + 8 + g) * 4 + wn] = ph;
            }
        }
        __syncthreads();
        if (tid < 64)
            g_scores[(size_t)b * S_ + s0 + tid] =
                sred[tid*4] + sred[tid*4+1] + sred[tid*4+2] + sred[tid*4+3];
        __syncthreads();
    }
}

// ---------------- K3: softmax over S ----------------
__global__ void k_softmax() {
    __shared__ float red[8];
    int b = blockIdx.x, t = threadIdx.x;
    float v[8], m = -1e30f;
#pragma unroll
    for (int i = 0; i < 8; i++) { v[i] = g_scores[(size_t)b*S_ + i*256 + t]; m = fmaxf(m, v[i]); }
    for (int o = 16; o; o >>= 1) m = fmaxf(m, __shfl_xor_sync(0xffffffffu, m, o));
    if ((t & 31) == 0) red[t >> 5] = m;
    __syncthreads();
    m = red[0];
#pragma unroll
    for (int i = 1; i < 8; i++) m = fmaxf(m, red[i]);
    __syncthreads();
    float s = 0.f;
#pragma unroll
    for (int i = 0; i < 8; i++) { v[i] = expf(v[i] - m); s += v[i]; }
    for (int o = 16; o; o >>= 1) s += __shfl_xor_sync(0xffffffffu, s, o);
    if ((t & 31) == 0) red[t >> 5] = s;
    __syncthreads();
    s = 0.f;
#pragma unroll
    for (int i = 0; i < 8; i++) s += red[i];
    float inv = 1.f / s;
#pragma unroll
    for (int i = 0; i < 8; i++) g_attn[(size_t)b*S_ + i*256 + t] = v[i] * inv;
}

// ---------------- K4: Xa partials: sum_s a[b,s] * enc[b,s,h], s-chunked ----------------
__global__ void k_xa(const float* __restrict__ enc) {
    __shared__ float a_s[256];
    int b = blockIdx.x, c = blockIdx.y, t = threadIdx.x;
    a_s[t] = g_attn[(size_t)b * S_ + c * 256 + t];
    __syncthreads();
    const float* ep = enc + ((size_t)b * S_ + c * 256) * H_ + t;
    float acc = 0.f;
#pragma unroll 8
    for (int s = 0; s < 256; s++) acc += a_s[s] * ep[(size_t)s * H_];
    g_partial[((size_t)c * B_ + b) * H_ + t] = acc;
}

// ---------------- K5: res = concat(emb[inp], Xa) @ W3 + b3 ----------------
__global__ void k_res(const int* __restrict__ inp, const float* __restrict__ emb,
                      const float* __restrict__ W3, const float* __restrict__ b3) {
    __shared__ float xa[H_], es[H_];
    int b = blockIdx.x, k = threadIdx.x;
    float s = 0.f;
#pragma unroll
    for (int c = 0; c < 8; c++) s += g_partial[((size_t)c * B_ + b) * H_ + k];
    xa[k] = s;
    es[k] = emb[(size_t)inp[b] * H_ + k];
    __syncthreads();
    float acc = b3[k];
#pragma unroll 8
    for (int h = 0; h < H_; h++) acc += es[h] * W3[h * H_ + k];
#pragma unroll 8
    for (int h = 0; h < H_; h++) acc += xa[h] * W3[(H_ + h) * H_ + k];
    g_res[b * H_ + k] = acc;
}

// ---------------- K6/K7: GRU cell (fp32), gate order (r,z,n) ----------------
__global__ void k_gru(const float* __restrict__ hprev, const float* __restrict__ Wih,
                      const float* __restrict__ Whh, const float* __restrict__ bih,
                      const float* __restrict__ bhh, int layer) {
    __shared__ __align__(16) float xs[H_], hs[H_];
    int b = blockIdx.x, j = threadIdx.x;
    const float* x = (layer == 0) ? g_res : g_h0;
    float* hout    = (layer == 0) ? g_h0  : g_h1;
    xs[j] = x[b * H_ + j];
    hs[j] = hprev[b * H_ + j];
    __syncthreads();
    const float4* wir = (const float4*)(Wih + (size_t)j * H_);
    const float4* wiz = (const float4*)(Wih + (size_t)(j + 256) * H_);
    const float4* win = (const float4*)(Wih + (size_t)(j + 512) * H_);
    const float4* whr = (const float4*)(Whh + (size_t)j * H_);
    const float4* whz = (const float4*)(Whh + (size_t)(j + 256) * H_);
    const float4* whn = (const float4*)(Whh + (size_t)(j + 512) * H_);
    const float4* xs4 = (const float4*)xs;
    const float4* hs4 = (const float4*)hs;
    float gir = bih[j], giz = bih[j + 256], gin = bih[j + 512];
    float ghr = bhh[j], ghz = bhh[j + 256], ghn = bhh[j + 512];
#pragma unroll 8
    for (int i = 0; i < 64; i++) {
        float4 xv = xs4[i], hv = hs4[i], a;
        a = wir[i]; gir += xv.x*a.x + xv.y*a.y + xv.z*a.z + xv.w*a.w;
        a = wiz[i]; giz += xv.x*a.x + xv.y*a.y + xv.z*a.z + xv.w*a.w;
        a = win[i]; gin += xv.x*a.x + xv.y*a.y + xv.z*a.z + xv.w*a.w;
        a = whr[i]; ghr += hv.x*a.x + hv.y*a.y + hv.z*a.z + hv.w*a.w;
        a = whz[i]; ghz += hv.x*a.x + hv.y*a.y + hv.z*a.z + hv.w*a.w;
        a = whn[i]; ghn += hv.x*a.x + hv.y*a.y + hv.z*a.z + hv.w*a.w;
    }
    float r = 1.f / (1.f + expf(-(gir + ghr)));
    float z = 1.f / (1.f + expf(-(giz + ghz)));
    float n = tanhf(gin + r * ghn);
    hout[b * H_ + j] = (1.f - z) * n + z * hs[j];
}

// ---------------- K8: logits = h1 @ Wout^T + bout  (bf16 mma), raw logits -> d_out ----------------
__global__ __launch_bounds__(256, 1) void k_logits(const float* __restrict__ Wout,
                                                   const float* __restrict__ bout,
                                                   float* __restrict__ out) {
    extern __shared__ unsigned char smem[];
    __nv_bfloat16* As = (__nv_bfloat16*)smem;                  // [128][KP] h1
    __nv_bfloat16* Bs = (__nv_bfloat16*)(smem + 128*KP*2);     // [128][KP] Wout tile
    const int tid = threadIdx.x;
    const int warp = tid >> 5, lane = tid & 31;
    const int g = lane >> 2, tg = lane & 3;
    const int wm = warp & 3, wn = warp >> 2;   // warp grid 4(M) x 2(N)
    const int v0 = blockIdx.x * 128;

    const float4* hv = (const float4*)g_h1;
    const float4* wv = (const float4*)(Wout + (size_t)v0 * H_);
    for (int i = tid; i < 8192; i += 256) {
        int e = i * 4, r = e >> 8, k = e & 255;
        float4 v = hv[i];
        *(__nv_bfloat162*)(As + r * KP + k)     = __floats2bfloat162_rn(v.x, v.y);
        *(__nv_bfloat162*)(As + r * KP + k + 2) = __floats2bfloat162_rn(v.z, v.w);
        v = wv[i];
        *(__nv_bfloat162*)(Bs + r * KP + k)     = __floats2bfloat162_rn(v.x, v.y);
        *(__nv_bfloat162*)(Bs + r * KP + k + 2) = __floats2bfloat162_rn(v.z, v.w);
    }
    __syncthreads();

    float acc[2][8][4] = {};
#pragma unroll
    for (int k0 = 0; k0 < 256; k0 += 16) {
        unsigned a[2][4], bb[8][2];
#pragma unroll
        for (int mi = 0; mi < 2; mi++) {
            int r = wm * 32 + mi * 16;
            a[mi][0] = *(const unsigned*)(As + (r + g)     * KP + k0     + tg*2);
            a[mi][1] = *(const unsigned*)(As + (r + g + 8) * KP + k0     + tg*2);
            a[mi][2] = *(const unsigned*)(As + (r + g)     * KP + k0 + 8 + tg*2);
            a[mi][3] = *(const unsigned*)(As + (r + g + 8) * KP + k0 + 8 + tg*2);
        }
#pragma unroll
        for (int ni = 0; ni < 8; ni++) {
            int n = wn * 64 + ni * 8 + g;
            bb[ni][0] = *(const unsigned*)(Bs + n * KP + k0     + tg*2);
            bb[ni][1] = *(const unsigned*)(Bs + n * KP + k0 + 8 + tg*2);
        }
#pragma unroll
        for (int mi = 0; mi < 2; mi++)
#pragma unroll
            for (int ni = 0; ni < 8; ni++)
                mma16816(acc[mi][ni], a[mi], bb[ni]);
    }

#pragma unroll
    for (int mi = 0; mi < 2; mi++) {
        int row = wm * 32 + mi * 16 + g;
#pragma unroll
        for (int ni = 0; ni < 8; ni++) {
            int c = wn * 64 + ni * 8 + tg * 2;
            int vc = v0 + c;
            float b0 = bout[vc], b1 = bout[vc + 1];
            out[(size_t)row * VSZ + vc]           = acc[mi][ni][0] + b0;
            out[(size_t)row * VSZ + vc + 1]       = acc[mi][ni][1] + b1;
            out[(size_t)(row + 8) * VSZ + vc]     = acc[mi][ni][2] + b0;
            out[(size_t)(row + 8) * VSZ + vc + 1] = acc[mi][ni][3] + b1;
        }
    }
}

// ---------------- K9: in-place log_softmax over vocab ----------------
__global__ void k_lsm(float* __restrict__ out) {
    __shared__ float red[8];
    int b = blockIdx.x, t = threadIdx.x;
    float* row = out + (size_t)b * VSZ;
    float m = -1e30f;
    for (int i = t; i < VSZ; i += 256) m = fmaxf(m, row[i]);
    for (int o = 16; o; o >>= 1) m = fmaxf(m, __shfl_xor_sync(0xffffffffu, m, o));
    if ((t & 31) == 0) red[t >> 5] = m;
    __syncthreads();
    m = red[0];
#pragma unroll
    for (int i = 1; i < 8; i++) m = fmaxf(m, red[i]);
    __syncthreads();
    float s = 0.f;
    for (int i = t; i < VSZ; i += 256) s += expf(row[i] - m);
    for (int o = 16; o; o >>= 1) s += __shfl_xor_sync(0xffffffffu, s, o);
    if ((t & 31) == 0) red[t >> 5] = s;
    __syncthreads();
    s = 0.f;
#pragma unroll
    for (int i = 0; i < 8; i++) s += red[i];
    float lse = m + logf(s);
    for (int i = t; i < VSZ; i += 256) row[i] -= lse;
}

// ---------------- K10: copy new_hidden into d_out tail ----------------
__global__ void k_copy_hidden(float* __restrict__ dst) {
    int b = blockIdx.x, l = blockIdx.y, t = threadIdx.x;
    const float* src = l ? g_h1 : g_h0;
    dst[(size_t)l * B_ * H_ + b * H_ + t] = src[b * H_ + t];
}

// ---------------- host launcher ----------------
extern "C" void kernel_launch(void* const* d_in, const int* in_sizes, int n_in,
                              void* d_out, int out_size) {
    const int*   inp    = (const int*)  d_in[0];
    const float* hidden = (const float*)d_in[1];
    const float* enc    = (const float*)d_in[2];
    const float* emb    = (const float*)d_in[3];
    const float* W1     = (const float*)d_in[4];
    const float* W2     = (const float*)d_in[5];
    const float* W3     = (const float*)d_in[6];
    const float* b2     = (const float*)d_in[7];
    const float* b3     = (const float*)d_in[8];
    const float* Vp     = (const float*)d_in[9];
    const float* Wih0   = (const float*)d_in[10];
    const float* Whh0   = (const float*)d_in[11];
    const float* bih0   = (const float*)d_in[12];
    const float* bhh0   = (const float*)d_in[13];
    const float* Wih1   = (const float*)d_in[14];
    const float* Whh1   = (const float*)d_in[15];
    const float* bih1   = (const float*)d_in[16];
    const float* bhh1   = (const float*)d_in[17];
    const float* Wout   = (const float*)d_in[18];
    const float* bout   = (const float*)d_in[19];
    float* out = (float*)d_out;

    cudaFuncSetAttribute(k_attn,   cudaFuncAttributeMaxDynamicSharedMemorySize, ATTN_SMEM);
    cudaFuncSetAttribute(k_logits, cudaFuncAttributeMaxDynamicSharedMemorySize, LOGITS_SMEM);

    k_convW1<<<dim3(8, 8), dim3(32, 32)>>>(W1);
    k_w2h<<<B_, 256>>>(hidden, W2, b2);
    k_attn<<<dim3(4, B_), 256, ATTN_SMEM>>>(enc, Vp);
    k_softmax<<<B_, 256>>>();
    k_xa<<<dim3(B_, 8), 256>>>(enc);
    k_res<<<B_, 256>>>(inp, emb, W3, b3);
    k_gru<<<B_, 256>>>(hidden,             Wih0, Whh0, bih0, bhh0, 0);
    k_gru<<<B_, 256>>>(hidden + B_ * H_,   Wih1, Whh1, bih1, bhh1, 1);
    k_logits<<<VSZ / 128, 256, LOGITS_SMEM>>>(Wout, bout, out);
    k_lsm<<<B_, 256>>>(out);
    if (out_size >= VSZ * B_ + 2 * B_ * H_) {
        k_copy_hidden<<<dim3(B_, 2), 256>>>(out + (size_t)VSZ * B_);
    }
}

// round 4
// speedup vs baseline: 1.2351x; 1.2351x over previous
#include <cuda_runtime.h>
#include <cuda_bf16.h>
#include <math.h>

#define B_   128
#define S_   2048
#define H_   256
#define VSZ  32000
#define KP   264   // padded smem row stride (bf16 elems)

// attn smem: Bs(256*KP*2) + As(128*KP*2) + w2h(1024) + V(1024) + sred(2048) + ws(512) + red(32)
#define ATTN_SMEM   (256*KP*2 + 128*KP*2 + 1024 + 1024 + 2048 + 512 + 32)
#define LOGITS_SMEM (128*KP*2 + 128*KP*2)

// ---------------- scratch ----------------
__device__ __align__(16) float g_xT[(H_+H_)*B_];      // [512][128] concat(emb, Xa) transposed
__device__ __align__(16) float g_w2hT[H_*B_];         // [256][128]
__device__ __align__(16) float g_resT[H_*B_];         // [256][128]
__device__ __align__(16) float g_hT[2*H_*B_];         // hidden transposed [2][256][128]
__device__ __align__(16) float g_h0T[H_*B_];
__device__ __align__(16) float g_h1T[H_*B_];
__device__ __align__(16) float g_h1[B_*H_];           // row-major for logits
__device__ __align__(16) __nv_bfloat16 g_W1T[H_*H_];

__device__ __forceinline__ float tanhfast(float x) {
    float y; asm("tanh.approx.f32 %0, %1;" : "=f"(y) : "f"(x)); return y;
}

__device__ __forceinline__ void mma16816(float (&d)[4], const unsigned (&a)[4], const unsigned (&b)[2]) {
    asm volatile(
        "mma.sync.aligned.m16n8k16.row.col.f32.bf16.bf16.f32 "
        "{%0,%1,%2,%3}, {%4,%5,%6,%7}, {%8,%9}, {%0,%1,%2,%3};\n"
        : "+f"(d[0]), "+f"(d[1]), "+f"(d[2]), "+f"(d[3])
        : "r"(a[0]), "r"(a[1]), "r"(a[2]), "r"(a[3]),
          "r"(b[0]), "r"(b[1]));
}

// ---------------- W1 -> W1T bf16 ----------------
__global__ void k_convW1(const float* __restrict__ W1) {
    __shared__ float tile[32][33];
    int kt = blockIdx.x, nt = blockIdx.y;
    int tx = threadIdx.x, ty = threadIdx.y;
    tile[ty][tx] = W1[(kt*32 + ty) * H_ + nt*32 + tx];
    __syncthreads();
    g_W1T[(nt*32 + ty) * H_ + kt*32 + tx] = __float2bfloat16(tile[tx][ty]);
}

// ---------------- transpose hidden -> g_hT[2][256][128] ----------------
__global__ void k_prep_h(const float* __restrict__ hidden) {
    int idx = blockIdx.x * 256 + threadIdx.x;        // 65536 total
    int l = idx >> 15, rem = idx & 32767;
    int j = rem >> 7, b = rem & 127;
    g_hT[idx] = hidden[l * (B_*H_) + b * H_ + j];
}

// ---------------- emb gather -> g_xT rows [0,256) ----------------
__global__ void k_prep_x(const int* __restrict__ inp, const float* __restrict__ emb) {
    int idx = blockIdx.x * 256 + threadIdx.x;        // 32768 total
    int h = idx >> 7, b = idx & 127;
    g_xT[h * B_ + b] = emb[(size_t)inp[b] * H_ + h];
}

// ---------------- weights-stationary col-GEMM: Y[k][b] = bias[k] + sum_h W[h][k] * Xt[h][b]
// grid 128 (k-chunks of 2), block 256 = (2 k) x (128 b)
__global__ void k_colgemm(const float* __restrict__ W, const float* __restrict__ bias,
                          const float* __restrict__ Xt, float* __restrict__ Yt, int Kdim) {
    __shared__ float Ws[2][512];
    int tid = threadIdx.x;
    int kl = tid >> 7, b = tid & 127;
    int k0 = blockIdx.x * 2;
    for (int i = tid; i < 2 * Kdim; i += 256) {
        int kk = (i >= Kdim) ? 1 : 0;
        int h = i - kk * Kdim;
        Ws[kk][h] = W[h * H_ + k0 + kk];
    }
    __syncthreads();
    float acc = bias[k0 + kl];
    const float* xp = Xt + b;
    const float* wp = Ws[kl];
#pragma unroll 8
    for (int h = 0; h < Kdim; h++) acc += wp[h] * xp[(size_t)h * B_];
    Yt[(k0 + kl) * B_ + b] = acc;
}

// ---------------- fused GRU layer (weights-stationary, all 6 gates + update) ----------------
// grid 128 (j-chunks of 2), block 256 = (2 j) x (128 b)
__global__ void k_gru(const float* __restrict__ Wih, const float* __restrict__ Whh,
                      const float* __restrict__ bih, const float* __restrict__ bhh,
                      const float* __restrict__ Xt, const float* __restrict__ HpT,
                      float* __restrict__ HoutT, float* __restrict__ Hrow) {
    __shared__ float Ws[12][256];
    int tid = threadIdx.x;
    int jl = tid >> 7, b = tid & 127;
    int j0 = blockIdx.x * 2;
    for (int i = tid; i < 12 * 256; i += 256) {
        int row = i >> 8, h = i & 255;
        int jl2 = row / 6, s = row % 6;
        int gate = s % 3, mat = s / 3;
        const float* Wm = mat ? Whh : Wih;
        Ws[row][h] = Wm[(size_t)(gate * H_ + j0 + jl2) * H_ + h];
    }
    __syncthreads();
    int j = j0 + jl;
    float a0 = bih[j], a1 = bih[j + H_], a2 = bih[j + 2*H_];
    float a3 = bhh[j], a4 = bhh[j + H_], a5 = bhh[j + 2*H_];
    const float* w0 = Ws[jl*6+0]; const float* w1 = Ws[jl*6+1]; const float* w2 = Ws[jl*6+2];
    const float* w3 = Ws[jl*6+3]; const float* w4 = Ws[jl*6+4]; const float* w5 = Ws[jl*6+5];
    const float* xp = Xt + b;
    const float* hp = HpT + b;
#pragma unroll 8
    for (int h = 0; h < H_; h++) {
        float x  = xp[(size_t)h * B_];
        float hh = hp[(size_t)h * B_];
        a0 += x * w0[h]; a1 += x * w1[h]; a2 += x * w2[h];
        a3 += hh * w3[h]; a4 += hh * w4[h]; a5 += hh * w5[h];
    }
    float r = 1.f / (1.f + expf(-(a0 + a3)));
    float z = 1.f / (1.f + expf(-(a1 + a4)));
    float n = tanhf(a2 + r * a5);
    float hprev = HpT[j * B_ + b];
    float ho = (1.f - z) * n + z * hprev;
    HoutT[j * B_ + b] = ho;
    if (Hrow) Hrow[b * H_ + j] = ho;
}

// ---------------- fused attention: scores + online softmax + Xa, one CTA per batch ----------------
__global__ __launch_bounds__(256, 1) void k_attn(const float* __restrict__ enc,
                                                 const float* __restrict__ Vp) {
    extern __shared__ unsigned char smem[];
    __nv_bfloat16* Bs = (__nv_bfloat16*)smem;                            // [256][KP]
    __nv_bfloat16* As = (__nv_bfloat16*)(smem + 256*KP*2);               // [128][KP]
    float* w2h_s = (float*)(smem + 256*KP*2 + 128*KP*2);                 // [256]
    float* V_s   = w2h_s + 256;                                          // [256]
    float* sred  = V_s + 256;                                            // [128][4]
    float* ws    = sred + 512;                                           // [128]
    float* red   = ws + 128;                                             // [8]

    const int tid  = threadIdx.x;
    const int warp = tid >> 5, lane = tid & 31;
    const int g = lane >> 2, tg = lane & 3;
    const int wm = warp & 1, wn = warp >> 1;     // 2(M) x 4(N)
    const int b = blockIdx.x;

    // stationary loads
    const uint4* src = (const uint4*)g_W1T;
    for (int i = tid; i < 8192; i += 256) {
        int e = i * 8, n = e >> 8, k = e & 255;
        *(uint4*)(Bs + n * KP + k) = src[i];
    }
    w2h_s[tid] = g_w2hT[tid * B_ + b];
    V_s[tid]   = Vp[tid];

    float m_run = -1e30f, s_run = 0.f, xacc = 0.f;

    for (int t = 0; t < 16; t++) {
        const int s0 = t * 128;
        __syncthreads();   // protect As/ws from previous tile readers; covers stationary loads at t=0
        const float4* ev = (const float4*)(enc + ((size_t)b * S_ + s0) * H_);
        for (int i = tid; i < 8192; i += 256) {
            int e = i * 4, r = e >> 8, k = e & 255;
            float4 v = ev[i];
            *(__nv_bfloat162*)(As + r * KP + k)     = __floats2bfloat162_rn(v.x, v.y);
            *(__nv_bfloat162*)(As + r * KP + k + 2) = __floats2bfloat162_rn(v.z, v.w);
        }
        __syncthreads();

        float acc[4][8][4] = {};
#pragma unroll
        for (int k0 = 0; k0 < 256; k0 += 16) {
            unsigned a[4][4], bb[8][2];
#pragma unroll
            for (int mi = 0; mi < 4; mi++) {
                int r = wm * 64 + mi * 16;
                a[mi][0] = *(const unsigned*)(As + (r + g)     * KP + k0     + tg*2);
                a[mi][1] = *(const unsigned*)(As + (r + g + 8) * KP + k0     + tg*2);
                a[mi][2] = *(const unsigned*)(As + (r + g)     * KP + k0 + 8 + tg*2);
                a[mi][3] = *(const unsigned*)(As + (r + g + 8) * KP + k0 + 8 + tg*2);
            }
#pragma unroll
            for (int ni = 0; ni < 8; ni++) {
                int n = wn * 64 + ni * 8 + g;
                bb[ni][0] = *(const unsigned*)(Bs + n * KP + k0     + tg*2);
                bb[ni][1] = *(const unsigned*)(Bs + n * KP + k0 + 8 + tg*2);
            }
#pragma unroll
            for (int mi = 0; mi < 4; mi++)
#pragma unroll
                for (int ni = 0; ni < 8; ni++)
                    mma16816(acc[mi][ni], a[mi], bb[ni]);
        }

        // epilogue: tanh(+w2h) * V, partial reduce over H
#pragma unroll
        for (int mi = 0; mi < 4; mi++) {
            float pl = 0.f, ph = 0.f;
#pragma unroll
            for (int ni = 0; ni < 8; ni++) {
                int c = wn * 64 + ni * 8 + tg * 2;
                float v0 = V_s[c], v1 = V_s[c+1];
                float u0 = w2h_s[c], u1 = w2h_s[c+1];
                pl += v0 * tanhfast(acc[mi][ni][0] + u0) + v1 * tanhfast(acc[mi][ni][1] + u1);
                ph += v0 * tanhfast(acc[mi][ni][2] + u0) + v1 * tanhfast(acc[mi][ni][3] + u1);
            }
            pl += __shfl_xor_sync(0xffffffffu, pl, 1); pl += __shfl_xor_sync(0xffffffffu, pl, 2);
            ph += __shfl_xor_sync(0xffffffffu, ph, 1); ph += __shfl_xor_sync(0xffffffffu, ph, 2);
            if (tg == 0) {
                int r = wm * 64 + mi * 16;
                sred[(r + g)     * 4 + wn] = pl;
                sred[(r + g + 8) * 4 + wn] = ph;
            }
        }
        __syncthreads();

        // scores + online softmax update
        if (tid < 128) {
            float v = sred[tid*4] + sred[tid*4+1] + sred[tid*4+2] + sred[tid*4+3];
            ws[tid] = v;
            float mx = v;
#pragma unroll
            for (int o = 16; o; o >>= 1) mx = fmaxf(mx, __shfl_xor_sync(0xffffffffu, mx, o));
            if (lane == 0) red[warp] = mx;
        }
        __syncthreads();
        float tmax = fmaxf(fmaxf(red[0], red[1]), fmaxf(red[2], red[3]));
        float m2 = fmaxf(m_run, tmax);
        float scale = __expf(m_run - m2);
        if (tid < 128) {
            float e = __expf(ws[tid] - m2);
            ws[tid] = e;
            float ssum = e;
#pragma unroll
            for (int o = 16; o; o >>= 1) ssum += __shfl_xor_sync(0xffffffffu, ssum, o);
            if (lane == 0) red[4 + warp] = ssum;
        }
        __syncthreads();
        float tsum = red[4] + red[5] + red[6] + red[7];
        s_run = s_run * scale + tsum;
        m_run = m2;
        xacc *= scale;
        const __nv_bfloat16* ap = As + tid;
#pragma unroll 8
        for (int r = 0; r < 128; r++)
            xacc += ws[r] * __bfloat162float(ap[r * KP]);
    }
    // Xa -> transposed x buffer rows [256, 512)
    g_xT[(size_t)(H_ + tid) * B_ + b] = xacc / s_run;
}

// ---------------- logits = h1 @ Wout^T + bout (bf16 mma) ----------------
__global__ __launch_bounds__(256, 1) void k_logits(const float* __restrict__ Wout,
                                                   const float* __restrict__ bout,
                                                   float* __restrict__ out) {
    extern __shared__ unsigned char smem[];
    __nv_bfloat16* As = (__nv_bfloat16*)smem;                  // [128][KP] h1
    __nv_bfloat16* Bs = (__nv_bfloat16*)(smem + 128*KP*2);     // [128][KP] Wout tile
    const int tid = threadIdx.x;
    const int warp = tid >> 5, lane = tid & 31;
    const int g = lane >> 2, tg = lane & 3;
    const int wm = warp & 3, wn = warp >> 2;   // 4(M) x 2(N)
    const int v0 = blockIdx.x * 128;

    const float4* hv = (const float4*)g_h1;
    const float4* wv = (const float4*)(Wout + (size_t)v0 * H_);
    for (int i = tid; i < 8192; i += 256) {
        int e = i * 4, r = e >> 8, k = e & 255;
        float4 v = hv[i];
        *(__nv_bfloat162*)(As + r * KP + k)     = __floats2bfloat162_rn(v.x, v.y);
        *(__nv_bfloat162*)(As + r * KP + k + 2) = __floats2bfloat162_rn(v.z, v.w);
        v = wv[i];
        *(__nv_bfloat162*)(Bs + r * KP + k)     = __floats2bfloat162_rn(v.x, v.y);
        *(__nv_bfloat162*)(Bs + r * KP + k + 2) = __floats2bfloat162_rn(v.z, v.w);
    }
    __syncthreads();

    float acc[2][8][4] = {};
#pragma unroll
    for (int k0 = 0; k0 < 256; k0 += 16) {
        unsigned a[2][4], bb[8][2];
#pragma unroll
        for (int mi = 0; mi < 2; mi++) {
            int r = wm * 32 + mi * 16;
            a[mi][0] = *(const unsigned*)(As + (r + g)     * KP + k0     + tg*2);
            a[mi][1] = *(const unsigned*)(As + (r + g + 8) * KP + k0     + tg*2);
            a[mi][2] = *(const unsigned*)(As + (r + g)     * KP + k0 + 8 + tg*2);
            a[mi][3] = *(const unsigned*)(As + (r + g + 8) * KP + k0 + 8 + tg*2);
        }
#pragma unroll
        for (int ni = 0; ni < 8; ni++) {
            int n = wn * 64 + ni * 8 + g;
            bb[ni][0] = *(const unsigned*)(Bs + n * KP + k0     + tg*2);
            bb[ni][1] = *(const unsigned*)(Bs + n * KP + k0 + 8 + tg*2);
        }
#pragma unroll
        for (int mi = 0; mi < 2; mi++)
#pragma unroll
            for (int ni = 0; ni < 8; ni++)
                mma16816(acc[mi][ni], a[mi], bb[ni]);
    }

#pragma unroll
    for (int mi = 0; mi < 2; mi++) {
        int row = wm * 32 + mi * 16 + g;
#pragma unroll
        for (int ni = 0; ni < 8; ni++) {
            int c = wn * 64 + ni * 8 + tg * 2;
            int vc = v0 + c;
            float b0 = bout[vc], b1 = bout[vc + 1];
            out[(size_t)row * VSZ + vc]           = acc[mi][ni][0] + b0;
            out[(size_t)row * VSZ + vc + 1]       = acc[mi][ni][1] + b1;
            out[(size_t)(row + 8) * VSZ + vc]     = acc[mi][ni][2] + b0;
            out[(size_t)(row + 8) * VSZ + vc + 1] = acc[mi][ni][3] + b1;
        }
    }
}

// ---------------- in-place log_softmax over vocab ----------------
__global__ void k_lsm(float* __restrict__ out) {
    __shared__ float red[8];
    int b = blockIdx.x, t = threadIdx.x;
    float* row = out + (size_t)b * VSZ;
    float m = -1e30f;
    for (int i = t; i < VSZ; i += 256) m = fmaxf(m, row[i]);
    for (int o = 16; o; o >>= 1) m = fmaxf(m, __shfl_xor_sync(0xffffffffu, m, o));
    if ((t & 31) == 0) red[t >> 5] = m;
    __syncthreads();
    m = red[0];
#pragma unroll
    for (int i = 1; i < 8; i++) m = fmaxf(m, red[i]);
    __syncthreads();
    float s = 0.f;
    for (int i = t; i < VSZ; i += 256) s += __expf(row[i] - m);
    for (int o = 16; o; o >>= 1) s += __shfl_xor_sync(0xffffffffu, s, o);
    if ((t & 31) == 0) red[t >> 5] = s;
    __syncthreads();
    s = 0.f;
#pragma unroll
    for (int i = 0; i < 8; i++) s += red[i];
    float lse = m + logf(s);
    for (int i = t; i < VSZ; i += 256) row[i] -= lse;
}

// ---------------- copy new_hidden (from transposed) ----------------
__global__ void k_copy_hidden(float* __restrict__ dst) {
    int idx = blockIdx.x * 256 + threadIdx.x;     // 65536
    int l = idx >> 15, rem = idx & 32767;
    int b = rem >> 8, j = rem & 255;
    const float* src = l ? g_h1T : g_h0T;
    dst[idx] = src[j * B_ + b];
}

// ---------------- host launcher ----------------
extern "C" void kernel_launch(void* const* d_in, const int* in_sizes, int n_in,
                              void* d_out, int out_size) {
    const int*   inp    = (const int*)  d_in[0];
    const float* hidden = (const float*)d_in[1];
    const float* enc    = (const float*)d_in[2];
    const float* emb    = (const float*)d_in[3];
    const float* W1     = (const float*)d_in[4];
    const float* W2     = (const float*)d_in[5];
    const float* W3     = (const float*)d_in[6];
    const float* b2     = (const float*)d_in[7];
    const float* b3     = (const float*)d_in[8];
    const float* Vp     = (const float*)d_in[9];
    const float* Wih0   = (const float*)d_in[10];
    const float* Whh0   = (const float*)d_in[11];
    const float* bih0   = (const float*)d_in[12];
    const float* bhh0   = (const float*)d_in[13];
    const float* Wih1   = (const float*)d_in[14];
    const float* Whh1   = (const float*)d_in[15];
    const float* bih1   = (const float*)d_in[16];
    const float* bhh1   = (const float*)d_in[17];
    const float* Wout   = (const float*)d_in[18];
    const float* bout   = (const float*)d_in[19];
    float* out = (float*)d_out;

    cudaFuncSetAttribute(k_attn,   cudaFuncAttributeMaxDynamicSharedMemorySize, ATTN_SMEM);
    cudaFuncSetAttribute(k_logits, cudaFuncAttributeMaxDynamicSharedMemorySize, LOGITS_SMEM);

    float* g_hT_p;    cudaGetSymbolAddress((void**)&g_hT_p,   g_hT);
    float* g_w2hT_p;  cudaGetSymbolAddress((void**)&g_w2hT_p, g_w2hT);
    float* g_xT_p;    cudaGetSymbolAddress((void**)&g_xT_p,   g_xT);
    float* g_resT_p;  cudaGetSymbolAddress((void**)&g_resT_p, g_resT);
    float* g_h0T_p;   cudaGetSymbolAddress((void**)&g_h0T_p,  g_h0T);
    float* g_h1T_p;   cudaGetSymbolAddress((void**)&g_h1T_p,  g_h1T);
    float* g_h1_p;    cudaGetSymbolAddress((void**)&g_h1_p,   g_h1);

    k_convW1<<<dim3(8, 8), dim3(32, 32)>>>(W1);
    k_prep_h<<<256, 256>>>(hidden);
    k_prep_x<<<128, 256>>>(inp, emb);
    k_colgemm<<<128, 256>>>(W2, b2, g_hT_p + H_*B_, g_w2hT_p, 256);   // w2h
    k_attn<<<B_, 256, ATTN_SMEM>>>(enc, Vp);                          // scores+softmax+Xa
    k_colgemm<<<128, 256>>>(W3, b3, g_xT_p, g_resT_p, 512);           // res
    k_gru<<<128, 256>>>(Wih0, Whh0, bih0, bhh0, g_resT_p, g_hT_p,         g_h0T_p, (float*)0);
    k_gru<<<128, 256>>>(Wih1, Whh1, bih1, bhh1, g_h0T_p, g_hT_p + H_*B_,  g_h1T_p, g_h1_p);
    k_logits<<<VSZ / 128, 256, LOGITS_SMEM>>>(Wout, bout, out);
    k_lsm<<<B_, 256>>>(out);
    if (out_size >= VSZ * B_ + 2 * B_ * H_) {
        k_copy_hidden<<<256, 256>>>(out + (size_t)VSZ * B_);
    }
}